// round 3
// baseline (speedup 1.0000x reference)
#include <cuda_runtime.h>

#define V_VOCAB 500000
#define D 128
#define M_MEM 1000
#define L_MEM 64
#define L_X 64
#define C_N 100
#define L_C 32
#define L_Y 32
#define N_MEMS (M_MEM + 1)            /* 1001: [xs, mems(0..999)] */
#define OUT_ROWS (1 + C_N)            /* 101 */
#define MAX_NORM 10.0f
#define RENORM_EPS 1e-7f
#define COS_EPS 1e-8f

// Scratch: row 0 = xs encoding, rows 1..1000 = mems encodings. 512.5 KB.
__device__ float g_enc[(size_t)N_MEMS * D];

// ---------------------------------------------------------------------------
// Encode body, L known at compile time so the gather loop fully unrolls and
// all L/8 row loads per warp are in flight simultaneously.
// 256 threads = 8 warps; warp w handles tokens w, w+8, w+16, ...
// ---------------------------------------------------------------------------
template <int L>
__device__ __forceinline__ void encode_body(
    const int* __restrict__ seq,
    const float* __restrict__ lt, const float* __restrict__ freqs,
    float* __restrict__ dst)
{
    constexpr int NT = L / 8;  // tokens per warp

    __shared__ int   sh_idx[L];
    __shared__ float sh_w[L];
    __shared__ float sh_wred[2];
    __shared__ float sh_acc[8][D];

    int tid  = threadIdx.x;
    int warp = tid >> 5;
    int lane = tid & 31;

    // token ids + weights (first L threads), weight sumsq via warp reduce
    if (tid < L) {
        int idx = seq[tid];
        sh_idx[tid] = idx;
        float f = freqs[idx];
        sh_w[tid] = f;
        float ws = f * f;
        #pragma unroll
        for (int o = 16; o > 0; o >>= 1)
            ws += __shfl_xor_sync(0xffffffffu, ws, o);
        if (lane == 0) sh_wred[warp] = ws;
    }
    __syncthreads();

    float inv_wnorm = rsqrtf((L > 32) ? (sh_wred[0] + sh_wred[1]) : sh_wred[0]);

    // issue all row gathers up front (MLP = NT)
    float4 e[NT];
    int    tok[NT];
    #pragma unroll
    for (int k = 0; k < NT; k++) {
        tok[k] = warp + 8 * k;
        int idx = sh_idx[tok[k]];
        e[k] = *reinterpret_cast<const float4*>(lt + (size_t)idx * D + lane * 4);
    }

    float4 acc = make_float4(0.0f, 0.0f, 0.0f, 0.0f);
    #pragma unroll
    for (int k = 0; k < NT; k++) {
        float sq = e[k].x * e[k].x + e[k].y * e[k].y
                 + e[k].z * e[k].z + e[k].w * e[k].w;
        #pragma unroll
        for (int o = 16; o > 0; o >>= 1)
            sq += __shfl_xor_sync(0xffffffffu, sq, o);
        float n = sqrtf(sq);
        float scale = (n > MAX_NORM) ? (MAX_NORM / (n + RENORM_EPS)) : 1.0f;
        float wl = sh_w[tok[k]] * inv_wnorm * scale;
        acc.x += wl * e[k].x;
        acc.y += wl * e[k].y;
        acc.z += wl * e[k].z;
        acc.w += wl * e[k].w;
    }

    sh_acc[warp][lane * 4 + 0] = acc.x;
    sh_acc[warp][lane * 4 + 1] = acc.y;
    sh_acc[warp][lane * 4 + 2] = acc.z;
    sh_acc[warp][lane * 4 + 3] = acc.w;
    __syncthreads();

    if (tid < D) {
        float s = 0.0f;
        #pragma unroll
        for (int w = 0; w < 8; w++) s += sh_acc[w][tid];
        dst[tid] = s;
    }
}

// ---------------------------------------------------------------------------
// Kernel A: encode all 1102 sequences, fully parallel, no dependencies.
//   block 0          -> xs    -> g_enc row 0
//   blocks 1..1000   -> mems  -> g_enc rows 1..1000
//   block 1001       -> ys    -> out row OUT_ROWS
//   blocks 1002..    -> cands -> out rows OUT_ROWS+1 ..
// ---------------------------------------------------------------------------
__global__ __launch_bounds__(256) void encode_all(
    const int* __restrict__ xs, const int* __restrict__ mems,
    const int* __restrict__ ys, const int* __restrict__ cands,
    const float* __restrict__ lt, const float* __restrict__ freqs,
    float* __restrict__ out)
{
    int b = blockIdx.x;
    if (b == 0) {
        encode_body<L_X>(xs, lt, freqs, g_enc);
    } else if (b <= M_MEM) {
        encode_body<L_MEM>(mems + (size_t)(b - 1) * L_MEM, lt, freqs,
                           g_enc + (size_t)b * D);
    } else if (b == M_MEM + 1) {
        encode_body<L_Y>(ys, lt, freqs, out + (size_t)OUT_ROWS * D);
    } else {
        int c = b - M_MEM - 2;
        encode_body<L_C>(cands + (size_t)c * L_C, lt, freqs,
                         out + (size_t)(OUT_ROWS + 1 + c) * D);
    }
}

// ---------------------------------------------------------------------------
// Kernel B: sims + softmax + attention-weighted sum + xs_out broadcast.
// Single block, 512 threads. g_enc is L2-hot from kernel A.
// ---------------------------------------------------------------------------
__global__ __launch_bounds__(512) void finalize_kernel(float* __restrict__ out)
{
    __shared__ float sh_x[D];
    __shared__ float sims[N_MEMS];
    __shared__ float red[16];
    __shared__ float sh_stat[2];   // [0]=inv(nx*..) scratch/max, [1]=sum
    __shared__ float sh_nx;
    __shared__ float part[16][D];
    __shared__ float sh_lhs[D];

    int tid  = threadIdx.x;
    int warp = tid >> 5;
    int lane = tid & 31;

    // --- xs encoding + its norm ---
    if (tid < D) sh_x[tid] = g_enc[tid];
    __syncthreads();
    if (tid < D) {
        float v = sh_x[tid];
        float sq = v * v;
        #pragma unroll
        for (int o = 16; o > 0; o >>= 1)
            sq += __shfl_xor_sync(0xffffffffu, sq, o);
        if (lane == 0) red[warp] = sq;
    }
    __syncthreads();
    if (tid == 0) {
        float sq = red[0] + red[1] + red[2] + red[3];
        float nx = fmaxf(sqrtf(sq), COS_EPS);
        sh_nx = nx;
        sims[0] = sq / (nx * nx);   // xs-vs-xs sim -> logical index 0 is mem0!
    }
    __syncthreads();
    float nx = sh_nx;

    // sims layout in shared: sims[i] for i in 0..999 = mems, sims[1000] = xs.
    // (the xs self-sim above was written to sims[0]; move it)
    if (tid == 0) { sims[M_MEM] = sims[0]; }
    __syncthreads();

    // --- cosine sims for the 1000 mem rows, warp-per-row, 2-way unrolled ---
    float4 x4 = *reinterpret_cast<const float4*>(&sh_x[lane * 4]);
    for (int i0 = warp; i0 < M_MEM; i0 += 32) {
        int i1 = i0 + 16;
        const float4* r0 = reinterpret_cast<const float4*>(&g_enc[(size_t)(i0 + 1) * D]);
        float4 e0 = r0[lane];
        float dot0 = e0.x * x4.x + e0.y * x4.y + e0.z * x4.z + e0.w * x4.w;
        float sq0  = e0.x * e0.x + e0.y * e0.y + e0.z * e0.z + e0.w * e0.w;
        float dot1 = 0.0f, sq1 = 0.0f;
        if (i1 < M_MEM) {
            const float4* r1 = reinterpret_cast<const float4*>(&g_enc[(size_t)(i1 + 1) * D]);
            float4 e1 = r1[lane];
            dot1 = e1.x * x4.x + e1.y * x4.y + e1.z * x4.z + e1.w * x4.w;
            sq1  = e1.x * e1.x + e1.y * e1.y + e1.z * e1.z + e1.w * e1.w;
        }
        #pragma unroll
        for (int o = 16; o > 0; o >>= 1) {
            dot0 += __shfl_xor_sync(0xffffffffu, dot0, o);
            sq0  += __shfl_xor_sync(0xffffffffu, sq0, o);
            dot1 += __shfl_xor_sync(0xffffffffu, dot1, o);
            sq1  += __shfl_xor_sync(0xffffffffu, sq1, o);
        }
        if (lane == 0) {
            sims[i0] = dot0 / (nx * fmaxf(sqrtf(sq0), COS_EPS));
            if (i1 < M_MEM)
                sims[i1] = dot1 / (nx * fmaxf(sqrtf(sq1), COS_EPS));
        }
    }
    __syncthreads();

    // --- softmax max ---
    float lmx = -1e30f;
    for (int i = tid; i < N_MEMS; i += 512) lmx = fmaxf(lmx, sims[i]);
    #pragma unroll
    for (int o = 16; o > 0; o >>= 1)
        lmx = fmaxf(lmx, __shfl_xor_sync(0xffffffffu, lmx, o));
    if (lane == 0) red[warp] = lmx;
    __syncthreads();
    if (tid == 0) {
        float m = red[0];
        #pragma unroll
        for (int w = 1; w < 16; w++) m = fmaxf(m, red[w]);
        sh_stat[0] = m;
    }
    __syncthreads();
    float mx = sh_stat[0];

    // --- exp + sum ---
    float lsum = 0.0f;
    for (int i = tid; i < N_MEMS; i += 512) {
        float e = expf(sims[i] - mx);
        sims[i] = e;
        lsum += e;
    }
    #pragma unroll
    for (int o = 16; o > 0; o >>= 1)
        lsum += __shfl_xor_sync(0xffffffffu, lsum, o);
    if (lane == 0) red[warp] = lsum;
    __syncthreads();
    if (tid == 0) {
        float sm = 0.0f;
        #pragma unroll
        for (int w = 0; w < 16; w++) sm += red[w];
        sh_stat[1] = sm;
    }
    __syncthreads();
    float inv_sum = 1.0f / sh_stat[1];

    // --- weighted sum: 32 float4-lanes x 16 row-chunks, independent loads ---
    {
        int q = tid & 31;
        int chunk = tid >> 5;
        float4 acc = make_float4(0.0f, 0.0f, 0.0f, 0.0f);
        for (int i = chunk; i < N_MEMS; i += 16) {
            int r = (i < M_MEM) ? (i + 1) : 0;
            float4 e = *reinterpret_cast<const float4*>(&g_enc[(size_t)r * D + q * 4]);
            float w = sims[i];
            acc.x += w * e.x;
            acc.y += w * e.y;
            acc.z += w * e.z;
            acc.w += w * e.w;
        }
        part[chunk][q * 4 + 0] = acc.x;
        part[chunk][q * 4 + 1] = acc.y;
        part[chunk][q * 4 + 2] = acc.z;
        part[chunk][q * 4 + 3] = acc.w;
    }
    __syncthreads();

    if (tid < D) {
        float s = 0.0f;
        #pragma unroll
        for (int c = 0; c < 16; c++) s += part[c][tid];
        sh_lhs[tid] = s * inv_sum;
    }
    __syncthreads();

    // --- broadcast lhs to the 101 xs_out rows ---
    for (int j = tid; j < OUT_ROWS * D; j += 512)
        out[j] = sh_lhs[j & (D - 1)];
}

extern "C" void kernel_launch(void* const* d_in, const int* in_sizes, int n_in,
                              void* d_out, int out_size) {
    const int*   xs    = (const int*)d_in[0];
    const int*   mems  = (const int*)d_in[1];
    const int*   ys    = (const int*)d_in[2];
    const int*   cands = (const int*)d_in[3];
    const float* lt    = (const float*)d_in[4];
    const float* freqs = (const float*)d_in[5];
    float* out = (float*)d_out;

    encode_all<<<2 + M_MEM + C_N, 256>>>(xs, mems, ys, cands, lt, freqs, out);
    finalize_kernel<<<1, 512>>>(out);
}

// round 4
// speedup vs baseline: 1.7923x; 1.7923x over previous
#include <cuda_runtime.h>

#define V_VOCAB 500000
#define D 128
#define M_MEM 1000
#define L_MEM 64
#define L_X 64
#define C_N 100
#define L_C 32
#define L_Y 32
#define N_MEMS (M_MEM + 1)            /* 1001: row0=xs, rows1..1000=mems */
#define OUT_ROWS (1 + C_N)            /* 101 */
#define MAX_NORM 10.0f
#define RENORM_EPS 1e-7f
#define COS_EPS 1e-8f

// Scratch: row 0 = xs encoding, rows 1..1000 = mems encodings. 512.5 KB.
__device__ float g_enc[(size_t)N_MEMS * D];
// sims[i]: i in 0..999 -> mem i (enc row i+1); sims[1000] -> xs (enc row 0).
__device__ float g_sims[N_MEMS];

// ---------------------------------------------------------------------------
// Encode body, L compile-time so all L/8 row gathers per warp are in flight.
// 256 threads = 8 warps; warp w handles tokens w, w+8, ...
// ---------------------------------------------------------------------------
template <int L>
__device__ __forceinline__ void encode_body(
    const int* __restrict__ seq,
    const float* __restrict__ lt, const float* __restrict__ freqs,
    float* __restrict__ dst)
{
    constexpr int NT = L / 8;

    __shared__ int   sh_idx[L];
    __shared__ float sh_w[L];
    __shared__ float sh_wred[2];
    __shared__ float sh_acc[8][D];

    int tid  = threadIdx.x;
    int warp = tid >> 5;
    int lane = tid & 31;

    if (tid < L) {
        int idx = seq[tid];
        sh_idx[tid] = idx;
        float f = freqs[idx];
        sh_w[tid] = f;
        float ws = f * f;
        #pragma unroll
        for (int o = 16; o > 0; o >>= 1)
            ws += __shfl_xor_sync(0xffffffffu, ws, o);
        if (lane == 0) sh_wred[warp] = ws;
    }
    __syncthreads();

    float inv_wnorm = rsqrtf((L > 32) ? (sh_wred[0] + sh_wred[1]) : sh_wred[0]);

    float4 e[NT];
    int    tok[NT];
    #pragma unroll
    for (int k = 0; k < NT; k++) {
        tok[k] = warp + 8 * k;
        int idx = sh_idx[tok[k]];
        e[k] = *reinterpret_cast<const float4*>(lt + (size_t)idx * D + lane * 4);
    }

    float4 acc = make_float4(0.0f, 0.0f, 0.0f, 0.0f);
    #pragma unroll
    for (int k = 0; k < NT; k++) {
        float sq = e[k].x * e[k].x + e[k].y * e[k].y
                 + e[k].z * e[k].z + e[k].w * e[k].w;
        #pragma unroll
        for (int o = 16; o > 0; o >>= 1)
            sq += __shfl_xor_sync(0xffffffffu, sq, o);
        float n = sqrtf(sq);
        float scale = (n > MAX_NORM) ? (MAX_NORM / (n + RENORM_EPS)) : 1.0f;
        float wl = sh_w[tok[k]] * inv_wnorm * scale;
        acc.x += wl * e[k].x;
        acc.y += wl * e[k].y;
        acc.z += wl * e[k].z;
        acc.w += wl * e[k].w;
    }

    sh_acc[warp][lane * 4 + 0] = acc.x;
    sh_acc[warp][lane * 4 + 1] = acc.y;
    sh_acc[warp][lane * 4 + 2] = acc.z;
    sh_acc[warp][lane * 4 + 3] = acc.w;
    __syncthreads();

    if (tid < D) {
        float s = 0.0f;
        #pragma unroll
        for (int w = 0; w < 8; w++) s += sh_acc[w][tid];
        dst[tid] = s;
    }
}

// ---------------------------------------------------------------------------
// Kernel A: encode all 1102 sequences (fully independent).
// ---------------------------------------------------------------------------
__global__ __launch_bounds__(256) void encode_all(
    const int* __restrict__ xs, const int* __restrict__ mems,
    const int* __restrict__ ys, const int* __restrict__ cands,
    const float* __restrict__ lt, const float* __restrict__ freqs,
    float* __restrict__ out)
{
    int b = blockIdx.x;
    if (b == 0) {
        encode_body<L_X>(xs, lt, freqs, g_enc);
    } else if (b <= M_MEM) {
        encode_body<L_MEM>(mems + (size_t)(b - 1) * L_MEM, lt, freqs,
                           g_enc + (size_t)b * D);
    } else if (b == M_MEM + 1) {
        encode_body<L_Y>(ys, lt, freqs, out + (size_t)OUT_ROWS * D);
    } else {
        int c = b - M_MEM - 2;
        encode_body<L_C>(cands + (size_t)c * L_C, lt, freqs,
                         out + (size_t)(OUT_ROWS + 1 + c) * D);
    }
}

// ---------------------------------------------------------------------------
// Kernel B: cosine sims, one warp per row, 126 blocks x 8 warps.
// Each warp: one 512B row load + one interleaved 3-value shuffle reduce.
// ---------------------------------------------------------------------------
__global__ __launch_bounds__(256) void sims_kernel()
{
    int tid  = threadIdx.x;
    int warp = tid >> 5;
    int lane = tid & 31;
    int i = blockIdx.x * 8 + warp;         // sims index 0..1000
    if (i >= N_MEMS) return;

    int r = (i < M_MEM) ? (i + 1) : 0;     // enc row for this sim

    float4 x = *reinterpret_cast<const float4*>(&g_enc[lane * 4]);
    float4 e = *reinterpret_cast<const float4*>(&g_enc[(size_t)r * D + lane * 4]);

    float dot = e.x * x.x + e.y * x.y + e.z * x.z + e.w * x.w;
    float esq = e.x * e.x + e.y * e.y + e.z * e.z + e.w * e.w;
    float xsq = x.x * x.x + x.y * x.y + x.z * x.z + x.w * x.w;
    #pragma unroll
    for (int o = 16; o > 0; o >>= 1) {
        dot += __shfl_xor_sync(0xffffffffu, dot, o);
        esq += __shfl_xor_sync(0xffffffffu, esq, o);
        xsq += __shfl_xor_sync(0xffffffffu, xsq, o);
    }
    if (lane == 0) {
        float nx = fmaxf(sqrtf(xsq), COS_EPS);
        float nm = fmaxf(sqrtf(esq), COS_EPS);
        g_sims[i] = dot / (nx * nm);
    }
}

// ---------------------------------------------------------------------------
// Kernel C: softmax over 1001 sims + weighted sum + output writes.
// 1024 threads; weighted sum = 32 i-chunks x 32 float4-lanes (high MLP).
// ---------------------------------------------------------------------------
__global__ __launch_bounds__(1024) void finalize_kernel(float* __restrict__ out)
{
    __shared__ float sims[N_MEMS];
    __shared__ float red[32];
    __shared__ float sh_stat[2];
    __shared__ float part[32][D];
    __shared__ float sh_lhs[D];

    int tid  = threadIdx.x;
    int warp = tid >> 5;
    int lane = tid & 31;

    for (int i = tid; i < N_MEMS; i += 1024) sims[i] = g_sims[i];
    __syncthreads();

    // --- max ---
    float lmx = (tid < N_MEMS) ? sims[tid] : -1e30f;
    #pragma unroll
    for (int o = 16; o > 0; o >>= 1)
        lmx = fmaxf(lmx, __shfl_xor_sync(0xffffffffu, lmx, o));
    if (lane == 0) red[warp] = lmx;
    __syncthreads();
    if (tid == 0) {
        float m = red[0];
        #pragma unroll
        for (int w = 1; w < 32; w++) m = fmaxf(m, red[w]);
        sh_stat[0] = m;
    }
    __syncthreads();
    float mx = sh_stat[0];

    // --- exp + sum ---
    float lsum = 0.0f;
    for (int i = tid; i < N_MEMS; i += 1024) {
        float e = expf(sims[i] - mx);
        sims[i] = e;
        lsum += e;
    }
    #pragma unroll
    for (int o = 16; o > 0; o >>= 1)
        lsum += __shfl_xor_sync(0xffffffffu, lsum, o);
    if (lane == 0) red[warp] = lsum;
    __syncthreads();
    if (tid == 0) {
        float s = 0.0f;
        #pragma unroll
        for (int w = 0; w < 32; w++) s += red[w];
        sh_stat[1] = s;
    }
    __syncthreads();
    float inv_sum = 1.0f / sh_stat[1];

    // --- weighted sum: part[chunk][:] = sum over i-chunk of w_i * enc_row ---
    {
        int q = tid & 31;        // float4 slice of the 128-dim row
        int chunk = tid >> 5;    // 0..31
        float4 acc = make_float4(0.0f, 0.0f, 0.0f, 0.0f);
        for (int i = chunk; i < N_MEMS; i += 32) {
            int r = (i < M_MEM) ? (i + 1) : 0;
            float4 e = *reinterpret_cast<const float4*>(&g_enc[(size_t)r * D + q * 4]);
            float w = sims[i];
            acc.x += w * e.x;
            acc.y += w * e.y;
            acc.z += w * e.z;
            acc.w += w * e.w;
        }
        part[chunk][q * 4 + 0] = acc.x;
        part[chunk][q * 4 + 1] = acc.y;
        part[chunk][q * 4 + 2] = acc.z;
        part[chunk][q * 4 + 3] = acc.w;
    }
    __syncthreads();

    if (tid < D) {
        float s = 0.0f;
        #pragma unroll
        for (int c = 0; c < 32; c++) s += part[c][tid];
        sh_lhs[tid] = s * inv_sum;
    }
    __syncthreads();

    // --- broadcast lhs to the 101 xs_out rows ---
    for (int j = tid; j < OUT_ROWS * D; j += 1024)
        out[j] = sh_lhs[j & (D - 1)];
}

extern "C" void kernel_launch(void* const* d_in, const int* in_sizes, int n_in,
                              void* d_out, int out_size) {
    const int*   xs    = (const int*)d_in[0];
    const int*   mems  = (const int*)d_in[1];
    const int*   ys    = (const int*)d_in[2];
    const int*   cands = (const int*)d_in[3];
    const float* lt    = (const float*)d_in[4];
    const float* freqs = (const float*)d_in[5];
    float* out = (float*)d_out;

    encode_all<<<2 + M_MEM + C_N, 256>>>(xs, mems, ys, cands, lt, freqs, out);
    sims_kernel<<<(N_MEMS + 7) / 8, 256>>>();
    finalize_kernel<<<1, 1024>>>(out);
}